// round 3
// baseline (speedup 1.0000x reference)
#include <cuda_runtime.h>
#include <math.h>

// ---------------------------------------------------------------------------
// Mamba2 block, B=2, T=1024, D_MODEL=2048, D_STATE=64, HEADDIM=64, EXPAND=2
// D_INNER=4096, NHEADS=64, CONV_DIM=4224, D_IN_PROJ=8384
// Pipeline: LN -> GEMM1 -> conv+silu -> dt/dA -> sequential scan -> gate+RMS
//           -> GEMM2 (+residual)
// All fp32. Scratch in __device__ globals (no allocation).
// ---------------------------------------------------------------------------

#define B_     2
#define T_     1024
#define DM     2048
#define DIN    4096
#define DCONV  4224
#define DPROJ  8384
#define NH     64
#define NTOK   (B_ * T_)   // 2048

__device__ float g_u  [(size_t)NTOK * DM];
__device__ float g_zx [(size_t)NTOK * DPROJ];
__device__ float g_xbc[(size_t)NTOK * DCONV];
__device__ float g_dt [(size_t)NTOK * NH];
__device__ float g_dA [(size_t)NTOK * NH];
__device__ float g_y  [(size_t)NTOK * DIN];

__device__ __forceinline__ float sigmoidf_(float v) { return 1.f / (1.f + expf(-v)); }

// ---------------------------------------------------------------------------
// LayerNorm: one block per token row (D=2048)
// ---------------------------------------------------------------------------
__global__ void ln_kernel(const float* __restrict__ x,
                          const float* __restrict__ w,
                          const float* __restrict__ bb) {
    int r = blockIdx.x;
    const float* xr = x + (size_t)r * DM;
    float s = 0.f, s2 = 0.f;
    for (int i = threadIdx.x; i < DM; i += blockDim.x) {
        float v = xr[i]; s += v; s2 += v * v;
    }
    __shared__ float shs[32], shs2[32];
    int lane = threadIdx.x & 31, wid = threadIdx.x >> 5;
#pragma unroll
    for (int o = 16; o; o >>= 1) {
        s  += __shfl_xor_sync(0xffffffffu, s, o);
        s2 += __shfl_xor_sync(0xffffffffu, s2, o);
    }
    if (lane == 0) { shs[wid] = s; shs2[wid] = s2; }
    __syncthreads();
    __shared__ float mu_s, inv_s;
    if (threadIdx.x == 0) {
        float ts = 0.f, ts2 = 0.f;
        int nw = blockDim.x >> 5;
        for (int i = 0; i < nw; i++) { ts += shs[i]; ts2 += shs2[i]; }
        float mu = ts / DM;
        float var = ts2 / DM - mu * mu;
        mu_s = mu;
        inv_s = rsqrtf(var + 1e-5f);
    }
    __syncthreads();
    float mu = mu_s, inv = inv_s;
    for (int i = threadIdx.x; i < DM; i += blockDim.x)
        g_u[(size_t)r * DM + i] = (xr[i] - mu) * inv * w[i] + bb[i];
}

// ---------------------------------------------------------------------------
// SGEMM NT: C[m,n] = sum_k A[m,k] * Bw[n,k] (+Res[m,n])
// 128x128x8 tile, 256 threads, 8x8 microtile.
// ---------------------------------------------------------------------------
template<bool GUARD_N, bool RES>
__device__ __forceinline__ void sgemm_body(const float* __restrict__ A,
                                           const float* __restrict__ Bw,
                                           const float* __restrict__ Res,
                                           float* __restrict__ C,
                                           int M, int N, int K) {
    __shared__ __align__(16) float As[8][128];
    __shared__ __align__(16) float Bs[8][128];

    const int tid = threadIdx.x;
    const int m0 = blockIdx.y * 128;
    const int n0 = blockIdx.x * 128;

    const int lrow = tid >> 1;
    const int lcol = (tid & 1) << 2;

    const int tx = tid & 15;
    const int ty = tid >> 4;

    float acc[8][8];
#pragma unroll
    for (int i = 0; i < 8; i++)
#pragma unroll
        for (int j = 0; j < 8; j++) acc[i][j] = 0.f;

    int brow = n0 + lrow;
    bool bval = true;
    if (GUARD_N && brow >= N) { brow = 0; bval = false; }

    const float* Ap = A  + (size_t)(m0 + lrow) * K + lcol;
    const float* Bp = Bw + (size_t)brow * K + lcol;

    for (int k0 = 0; k0 < K; k0 += 8) {
        float4 av = *reinterpret_cast<const float4*>(Ap + k0);
        float4 bv = *reinterpret_cast<const float4*>(Bp + k0);
        if (GUARD_N && !bval) bv = make_float4(0.f, 0.f, 0.f, 0.f);
        __syncthreads();
        As[lcol + 0][lrow] = av.x; As[lcol + 1][lrow] = av.y;
        As[lcol + 2][lrow] = av.z; As[lcol + 3][lrow] = av.w;
        Bs[lcol + 0][lrow] = bv.x; Bs[lcol + 1][lrow] = bv.y;
        Bs[lcol + 2][lrow] = bv.z; Bs[lcol + 3][lrow] = bv.w;
        __syncthreads();
#pragma unroll
        for (int kk = 0; kk < 8; kk++) {
            float a[8], b[8];
            float4 t;
            t = *reinterpret_cast<const float4*>(&As[kk][ty * 4]);
            a[0] = t.x; a[1] = t.y; a[2] = t.z; a[3] = t.w;
            t = *reinterpret_cast<const float4*>(&As[kk][ty * 4 + 64]);
            a[4] = t.x; a[5] = t.y; a[6] = t.z; a[7] = t.w;
            t = *reinterpret_cast<const float4*>(&Bs[kk][tx * 4]);
            b[0] = t.x; b[1] = t.y; b[2] = t.z; b[3] = t.w;
            t = *reinterpret_cast<const float4*>(&Bs[kk][tx * 4 + 64]);
            b[4] = t.x; b[5] = t.y; b[6] = t.z; b[7] = t.w;
#pragma unroll
            for (int i = 0; i < 8; i++)
#pragma unroll
                for (int j = 0; j < 8; j++)
                    acc[i][j] = fmaf(a[i], b[j], acc[i][j]);
        }
    }

#pragma unroll
    for (int ih = 0; ih < 2; ih++) {
#pragma unroll
        for (int ii = 0; ii < 4; ii++) {
            int i = ih * 4 + ii;
            int m = m0 + ih * 64 + ty * 4 + ii;
#pragma unroll
            for (int jh = 0; jh < 2; jh++) {
                int n = n0 + jh * 64 + tx * 4;
                if (GUARD_N && n >= N) continue;   // N % 4 == 0, so full float4 valid
                float4 v;
                v.x = acc[i][jh * 4 + 0]; v.y = acc[i][jh * 4 + 1];
                v.z = acc[i][jh * 4 + 2]; v.w = acc[i][jh * 4 + 3];
                if (RES) {
                    float4 rv = *reinterpret_cast<const float4*>(Res + (size_t)m * N + n);
                    v.x += rv.x; v.y += rv.y; v.z += rv.z; v.w += rv.w;
                }
                *reinterpret_cast<float4*>(C + (size_t)m * N + n) = v;
            }
        }
    }
}

__global__ __launch_bounds__(256, 2)
void gemm1_kernel(const float* __restrict__ W) {
    sgemm_body<true, false>(g_u, W, nullptr, g_zx, NTOK, DPROJ, DM);
}

__global__ __launch_bounds__(256, 2)
void gemm2_kernel(const float* __restrict__ W,
                  const float* __restrict__ Res,
                  float* __restrict__ C) {
    sgemm_body<false, true>(g_y, W, Res, C, NTOK, DM, DIN);
}

// ---------------------------------------------------------------------------
// Depthwise causal conv (k=4) + SiLU on xBC channels. Thread = (channel),
// block.y = (batch, t-chunk).
// ---------------------------------------------------------------------------
#define CCHUNK 128
__global__ void conv_kernel(const float* __restrict__ cw,
                            const float* __restrict__ cb) {
    int c = blockIdx.x * blockDim.x + threadIdx.x;
    if (c >= DCONV) return;
    int b = blockIdx.y >> 3;       // 8 chunks of 128 over T=1024
    int chunk = blockIdx.y & 7;
    int t0 = chunk * CCHUNK;
    float w0 = cw[c * 4 + 0], w1 = cw[c * 4 + 1];
    float w2 = cw[c * 4 + 2], w3 = cw[c * 4 + 3];
    float bias = cb[c];
    const float* src = g_zx + (size_t)b * T_ * DPROJ + DIN + c;
    float* dst = g_xbc + (size_t)b * T_ * DCONV + c;
    float x0 = (t0 >= 3) ? src[(size_t)(t0 - 3) * DPROJ] : 0.f;
    float x1 = (t0 >= 2) ? src[(size_t)(t0 - 2) * DPROJ] : 0.f;
    float x2 = (t0 >= 1) ? src[(size_t)(t0 - 1) * DPROJ] : 0.f;
    for (int t = t0; t < t0 + CCHUNK; t++) {
        float x3 = src[(size_t)t * DPROJ];
        float v = bias + x0 * w0 + x1 * w1 + x2 * w2 + x3 * w3;
        v = v * sigmoidf_(v);
        dst[(size_t)t * DCONV] = v;
        x0 = x1; x1 = x2; x2 = x3;
    }
}

// ---------------------------------------------------------------------------
// dt = softplus(dt_raw + dt_bias), dA = exp(dt * -exp(A_log))
// ---------------------------------------------------------------------------
__global__ void dt_kernel(const float* __restrict__ dt_bias,
                          const float* __restrict__ A_log) {
    int r = blockIdx.x;
    int h = threadIdx.x;   // 64
    float raw = g_zx[(size_t)r * DPROJ + DIN + DCONV + h] + dt_bias[h];
    float dtv = (raw > 20.f) ? raw : log1pf(expf(raw));
    float Av = -expf(A_log[h]);
    g_dt[r * NH + h] = dtv;
    g_dA[r * NH + h] = expf(dtv * Av);
}

// ---------------------------------------------------------------------------
// Sequential selective scan. Block = (b, head), 64 threads (thread = p).
// State h[p][0..63] in registers; B/C/x staged via double-buffered SMEM,
// one __syncthreads per step. y[p] = h . C + D*x_in.
// ---------------------------------------------------------------------------
__global__ __launch_bounds__(64)
void scan_kernel(const float* __restrict__ Dvec) {
    int bh = blockIdx.x;
    int b = bh >> 6, hh = bh & 63;
    int p = threadIdx.x;

    __shared__ __align__(16) float sB[2][64];
    __shared__ __align__(16) float sC[2][64];
    __shared__ __align__(16) float sX[2][64];
    __shared__ float sS[2][2];   // [buf][0]=dA, [buf][1]=dt

    float st[64];
#pragma unroll
    for (int n = 0; n < 64; n++) st[n] = 0.f;
    float Dh = Dvec[hh];

    const size_t base = (size_t)b * T_ * DCONV;
    {   // preload t = 0
        sX[0][p] = g_xbc[base + hh * 64 + p];
        sB[0][p] = g_xbc[base + 4096 + p];
        sC[0][p] = g_xbc[base + 4160 + p];
        if (p < 2) {
            int rr = b * T_;
            sS[0][p] = (p == 0) ? g_dA[rr * NH + hh] : g_dt[rr * NH + hh];
        }
    }

    for (int t = 0; t < T_; t++) {
        int buf = t & 1;
        __syncthreads();
        if (t + 1 < T_) {
            size_t rq = base + (size_t)(t + 1) * DCONV;
            sX[buf ^ 1][p] = g_xbc[rq + hh * 64 + p];
            sB[buf ^ 1][p] = g_xbc[rq + 4096 + p];
            sC[buf ^ 1][p] = g_xbc[rq + 4160 + p];
            if (p < 2) {
                int rr = b * T_ + t + 1;
                sS[buf ^ 1][p] = (p == 0) ? g_dA[rr * NH + hh] : g_dt[rr * NH + hh];
            }
        }
        float dAv = sS[buf][0];
        float dtx = sS[buf][1] * sX[buf][p];
        float acc = 0.f;
#pragma unroll
        for (int q = 0; q < 16; q++) {
            float4 b4 = *reinterpret_cast<const float4*>(&sB[buf][q * 4]);
            float4 c4 = *reinterpret_cast<const float4*>(&sC[buf][q * 4]);
            st[q * 4 + 0] = st[q * 4 + 0] * dAv + dtx * b4.x;
            st[q * 4 + 1] = st[q * 4 + 1] * dAv + dtx * b4.y;
            st[q * 4 + 2] = st[q * 4 + 2] * dAv + dtx * b4.z;
            st[q * 4 + 3] = st[q * 4 + 3] * dAv + dtx * b4.w;
            acc = fmaf(st[q * 4 + 0], c4.x, acc);
            acc = fmaf(st[q * 4 + 1], c4.y, acc);
            acc = fmaf(st[q * 4 + 2], c4.z, acc);
            acc = fmaf(st[q * 4 + 3], c4.w, acc);
        }
        g_y[(size_t)(b * T_ + t) * DIN + hh * 64 + p] = acc + Dh * sX[buf][p];
    }
}

// ---------------------------------------------------------------------------
// y = y * silu(z); y = y * rsqrt(mean(y^2)+eps) * norm_w. Block per token.
// ---------------------------------------------------------------------------
__global__ void gate_rms_kernel(const float* __restrict__ norm_w) {
    int r = blockIdx.x;
    float ss = 0.f;
    for (int i = threadIdx.x; i < DIN; i += blockDim.x) {
        float zv = g_zx[(size_t)r * DPROJ + i];
        float g = g_y[(size_t)r * DIN + i] * zv * sigmoidf_(zv);
        g_y[(size_t)r * DIN + i] = g;
        ss += g * g;
    }
    __shared__ float sh[32];
    int lane = threadIdx.x & 31, wid = threadIdx.x >> 5;
#pragma unroll
    for (int o = 16; o; o >>= 1) ss += __shfl_xor_sync(0xffffffffu, ss, o);
    if (lane == 0) sh[wid] = ss;
    __syncthreads();
    __shared__ float sc;
    if (threadIdx.x == 0) {
        float tot = 0.f;
        int nw = blockDim.x >> 5;
        for (int i = 0; i < nw; i++) tot += sh[i];
        sc = rsqrtf(tot / DIN + 1e-5f);
    }
    __syncthreads();
    float s = sc;
    for (int i = threadIdx.x; i < DIN; i += blockDim.x)
        g_y[(size_t)r * DIN + i] *= s * norm_w[i];
}

// ---------------------------------------------------------------------------
// launch
// ---------------------------------------------------------------------------
extern "C" void kernel_launch(void* const* d_in, const int* in_sizes, int n_in,
                              void* d_out, int out_size) {
    const float* x          = (const float*)d_in[0];
    const float* ln_w       = (const float*)d_in[1];
    const float* ln_b       = (const float*)d_in[2];
    const float* in_proj_w  = (const float*)d_in[3];
    const float* conv_w     = (const float*)d_in[4];
    const float* conv_b     = (const float*)d_in[5];
    const float* dt_bias    = (const float*)d_in[6];
    const float* A_log      = (const float*)d_in[7];
    const float* Dv         = (const float*)d_in[8];
    const float* norm_w     = (const float*)d_in[9];
    const float* out_proj_w = (const float*)d_in[10];
    float* out = (float*)d_out;

    ln_kernel<<<NTOK, 256>>>(x, ln_w, ln_b);
    gemm1_kernel<<<dim3((DPROJ + 127) / 128, NTOK / 128), 256>>>(in_proj_w);
    conv_kernel<<<dim3((DCONV + 255) / 256, B_ * 8), 256>>>(conv_w, conv_b);
    dt_kernel<<<NTOK, NH>>>(dt_bias, A_log);
    scan_kernel<<<B_ * NH, 64>>>(Dv);
    gate_rms_kernel<<<NTOK, 256>>>(norm_w);
    gemm2_kernel<<<dim3(DM / 128, NTOK / 128), 256>>>(out_proj_w, x, out);
}

// round 5
// speedup vs baseline: 1.0379x; 1.0379x over previous
#include <cuda_runtime.h>
#include <math.h>
#include <stdint.h>

// ---------------------------------------------------------------------------
// Mamba2 block, B=2, T=1024, D_MODEL=2048, D_STATE=64, HEADDIM=64, EXPAND=2
// D_INNER=4096, NHEADS=64, CONV_DIM=4224, D_IN_PROJ=8384
// R4: same design as R3 but GEMM k-tile 16 -> 40KB *static* smem:
//     no cudaFuncSetAttribute / dynamic smem in kernel_launch (capture-risk
//     removal after container failure). tf32 mma.sync m16n8k8 GEMMs,
//     exact-fp32 dt side-channel, fp32 everything else.
// ---------------------------------------------------------------------------

#define B_     2
#define T_     1024
#define DM     2048
#define DIN    4096
#define DCONV  4224
#define DPROJ  8384
#define NH     64
#define NTOK   (B_ * T_)   // 2048

__device__ float g_u  [(size_t)NTOK * DM];
__device__ float g_zx [(size_t)NTOK * DPROJ];
__device__ float g_xbc[(size_t)NTOK * DCONV];
__device__ float g_dt [(size_t)NTOK * NH];
__device__ float g_dA [(size_t)NTOK * NH];
__device__ float g_y  [(size_t)NTOK * DIN];

__device__ __forceinline__ float sigmoidf_(float v) { return 1.f / (1.f + expf(-v)); }

__device__ __forceinline__ uint32_t f2tf(float x) {
    uint32_t r;
    asm("cvt.rna.tf32.f32 %0, %1;" : "=r"(r) : "f"(x));
    return r;
}
__device__ __forceinline__ uint32_t s2u(const void* p) {
    return (uint32_t)__cvta_generic_to_shared(p);
}
#define CPA16(dst, src) asm volatile("cp.async.cg.shared.global [%0], [%1], 16;" :: "r"(dst), "l"(src))
#define CPA_COMMIT()    asm volatile("cp.async.commit_group;")
#define CPA_WAIT0()     asm volatile("cp.async.wait_group 0;")

#define MMA8(d, a, b0v, b1v) asm volatile( \
    "mma.sync.aligned.m16n8k8.row.col.f32.tf32.tf32.f32 " \
    "{%0,%1,%2,%3},{%4,%5,%6,%7},{%8,%9},{%0,%1,%2,%3};" \
    : "+f"(d[0]), "+f"(d[1]), "+f"(d[2]), "+f"(d[3]) \
    : "r"(a[0]), "r"(a[1]), "r"(a[2]), "r"(a[3]), "r"(b0v), "r"(b1v))

// ---------------------------------------------------------------------------
// LayerNorm: one block per token row (D=2048)
// ---------------------------------------------------------------------------
__global__ void ln_kernel(const float* __restrict__ x,
                          const float* __restrict__ w,
                          const float* __restrict__ bb) {
    int r = blockIdx.x;
    const float* xr = x + (size_t)r * DM;
    float s = 0.f, s2 = 0.f;
    for (int i = threadIdx.x; i < DM; i += blockDim.x) {
        float v = xr[i]; s += v; s2 += v * v;
    }
    __shared__ float shs[32], shs2[32];
    int lane = threadIdx.x & 31, wid = threadIdx.x >> 5;
#pragma unroll
    for (int o = 16; o; o >>= 1) {
        s  += __shfl_xor_sync(0xffffffffu, s, o);
        s2 += __shfl_xor_sync(0xffffffffu, s2, o);
    }
    if (lane == 0) { shs[wid] = s; shs2[wid] = s2; }
    __syncthreads();
    __shared__ float mu_s, inv_s;
    if (threadIdx.x == 0) {
        float ts = 0.f, ts2 = 0.f;
        int nw = blockDim.x >> 5;
        for (int i = 0; i < nw; i++) { ts += shs[i]; ts2 += shs2[i]; }
        float mu = ts / DM;
        float var = ts2 / DM - mu * mu;
        mu_s = mu;
        inv_s = rsqrtf(var + 1e-5f);
    }
    __syncthreads();
    float mu = mu_s, inv = inv_s;
    for (int i = threadIdx.x; i < DM; i += blockDim.x)
        g_u[(size_t)r * DM + i] = (xr[i] - mu) * inv * w[i] + bb[i];
}

// ---------------------------------------------------------------------------
// tf32 tensor-core GEMM NT: C[m,n] = sum_k A[m,k]*Bw[n,k] (+Res)
// 128x128x16 CTA tile, 256 thr, warp tile 32x64, double-buffered cp.async.
// Static smem: 4 * 128*20 floats = 40960 bytes. Pitch 20 => conflict-free
// fragment LDS (banks (20*g+tg)%32 distinct) and 16B-aligned rows (80B).
// ---------------------------------------------------------------------------
#define GPITCH 20
#define GASZ   (128 * GPITCH)          // 2560 floats per tile array

template<bool GUARD_N, bool RES>
__device__ __forceinline__ void gemm_tf32(const float* __restrict__ A,
                                          const float* __restrict__ Bw,
                                          const float* __restrict__ Res,
                                          float* __restrict__ C,
                                          int M, int N, int K) {
    __shared__ __align__(16) float sm[4 * GASZ];   // 40960 bytes
    float* AsS[2] = { sm,            sm + 2 * GASZ };
    float* BsS[2] = { sm + GASZ,     sm + 3 * GASZ };

    const int tid  = threadIdx.x;
    const int lane = tid & 31;
    const int wid  = tid >> 5;
    const int g    = lane >> 2;
    const int tg   = lane & 3;
    const int wm0  = (wid & 3) * 32;
    const int wn0  = (wid >> 2) * 64;
    const int m0   = blockIdx.y * 128;
    const int n0   = blockIdx.x * 128;

    float acc[2][8][4];
#pragma unroll
    for (int i = 0; i < 2; i++)
#pragma unroll
        for (int j = 0; j < 8; j++)
#pragma unroll
            for (int q = 0; q < 4; q++) acc[i][j][q] = 0.f;

    // per-thread load: 2 x 16B for A, 2 x 16B for B (128 rows x 16 floats each)
    auto load_tile = [&](int st, int k0) {
#pragma unroll
        for (int i = 0; i < 2; i++) {
            int c = tid + 256 * i;
            int row = c >> 2, col4 = (c & 3) * 4;
            CPA16(s2u(&AsS[st][row * GPITCH + col4]),
                  A + (size_t)(m0 + row) * K + k0 + col4);
        }
#pragma unroll
        for (int i = 0; i < 2; i++) {
            int c = tid + 256 * i;
            int row = c >> 2, col4 = (c & 3) * 4;
            int br = n0 + row;
            if (GUARD_N && br >= N) br = N - 1;   // clamp; stores guarded
            CPA16(s2u(&BsS[st][row * GPITCH + col4]),
                  Bw + (size_t)br * K + k0 + col4);
        }
        CPA_COMMIT();
    };

    const int KT = K >> 4;
    load_tile(0, 0);

    for (int kt = 0; kt < KT; kt++) {
        int cur = kt & 1;
        CPA_WAIT0();
        __syncthreads();
        if (kt + 1 < KT) load_tile(cur ^ 1, (kt + 1) << 4);

        const float* Ac = AsS[cur];
        const float* Bc = BsS[cur];
#pragma unroll
        for (int k8 = 0; k8 < 2; k8++) {
            int kb = k8 * 8;
            uint32_t af[2][4];
#pragma unroll
            for (int i = 0; i < 2; i++) {
                const float* ap = &Ac[(wm0 + i * 16 + g) * GPITCH + kb + tg];
                af[i][0] = f2tf(ap[0]);
                af[i][1] = f2tf(ap[8 * GPITCH]);
                af[i][2] = f2tf(ap[4]);
                af[i][3] = f2tf(ap[8 * GPITCH + 4]);
            }
#pragma unroll
            for (int j = 0; j < 8; j++) {
                const float* bp = &Bc[(wn0 + j * 8 + g) * GPITCH + kb + tg];
                uint32_t b0 = f2tf(bp[0]);
                uint32_t b1 = f2tf(bp[4]);
                MMA8(acc[0][j], af[0], b0, b1);
                MMA8(acc[1][j], af[1], b0, b1);
            }
        }
    }
    __syncthreads();

    // epilogue
#pragma unroll
    for (int i = 0; i < 2; i++) {
        int m = m0 + wm0 + i * 16 + g;
#pragma unroll
        for (int j = 0; j < 8; j++) {
            int n = n0 + wn0 + j * 8 + 2 * tg;
            if (GUARD_N && n >= N) continue;
            float2 v0 = make_float2(acc[i][j][0], acc[i][j][1]);
            float2 v1 = make_float2(acc[i][j][2], acc[i][j][3]);
            if (RES) {
                float2 r0 = *(const float2*)&Res[(size_t)m * N + n];
                float2 r1 = *(const float2*)&Res[(size_t)(m + 8) * N + n];
                v0.x += r0.x; v0.y += r0.y;
                v1.x += r1.x; v1.y += r1.y;
            }
            *(float2*)&C[(size_t)m * N + n]       = v0;
            *(float2*)&C[(size_t)(m + 8) * N + n] = v1;
        }
    }
}

__global__ __launch_bounds__(256)
void gemm1_tc(const float* __restrict__ W) {
    gemm_tf32<true, false>(g_u, W, nullptr, g_zx, NTOK, DPROJ, DM);
}
__global__ __launch_bounds__(256)
void gemm2_tc(const float* __restrict__ W,
              const float* __restrict__ Res,
              float* __restrict__ C) {
    gemm_tf32<false, true>(g_y, W, Res, C, NTOK, DM, DIN);
}

// ---------------------------------------------------------------------------
// Exact fp32 dt: dtraw[t,h] = u[t,:] . W[8320+h,:], then softplus + dA.
// Block = 4 tokens x 64 heads; u rows in smem, W rows in registers.
// ---------------------------------------------------------------------------
#define DTTOK 4
__global__ __launch_bounds__(256)
void dtexact_kernel(const float* __restrict__ W,
                    const float* __restrict__ dt_bias,
                    const float* __restrict__ A_log) {
    __shared__ float su[DTTOK][DM];
    int t0 = blockIdx.x * DTTOK;
    int tid = threadIdx.x, lane = tid & 31, wid = tid >> 5;
    for (int i = tid; i < DTTOK * DM; i += 256) {
        int tt = i >> 11, k = i & (DM - 1);
        su[tt][k] = g_u[(size_t)(t0 + tt) * DM + k];
    }
    __syncthreads();
    const float* Wdt = W + (size_t)(DPROJ - NH) * DM;
    for (int hb = 0; hb < 8; hb++) {
        int h = hb * 8 + wid;
        const float* wr = Wdt + (size_t)h * DM;
        float wreg[64];
#pragma unroll
        for (int i = 0; i < 64; i++) wreg[i] = wr[lane + 32 * i];
#pragma unroll
        for (int tt = 0; tt < DTTOK; tt++) {
            float acc = 0.f;
#pragma unroll
            for (int i = 0; i < 64; i++)
                acc = fmaf(wreg[i], su[tt][lane + 32 * i], acc);
#pragma unroll
            for (int o = 16; o; o >>= 1)
                acc += __shfl_xor_sync(0xffffffffu, acc, o);
            if (lane == 0) {
                float raw = acc + dt_bias[h];
                float dtv = (raw > 20.f) ? raw : log1pf(expf(raw));
                float Av = -expf(A_log[h]);
                int r = t0 + tt;
                g_dt[r * NH + h] = dtv;
                g_dA[r * NH + h] = expf(dtv * Av);
            }
        }
    }
}

// ---------------------------------------------------------------------------
// Depthwise causal conv (k=4) + SiLU on xBC channels.
// ---------------------------------------------------------------------------
#define CCHUNK 128
__global__ void conv_kernel(const float* __restrict__ cw,
                            const float* __restrict__ cb) {
    int c = blockIdx.x * blockDim.x + threadIdx.x;
    if (c >= DCONV) return;
    int b = blockIdx.y >> 3;
    int chunk = blockIdx.y & 7;
    int t0 = chunk * CCHUNK;
    float w0 = cw[c * 4 + 0], w1 = cw[c * 4 + 1];
    float w2 = cw[c * 4 + 2], w3 = cw[c * 4 + 3];
    float bias = cb[c];
    const float* src = g_zx + (size_t)b * T_ * DPROJ + DIN + c;
    float* dst = g_xbc + (size_t)b * T_ * DCONV + c;
    float x0 = (t0 >= 3) ? src[(size_t)(t0 - 3) * DPROJ] : 0.f;
    float x1 = (t0 >= 2) ? src[(size_t)(t0 - 2) * DPROJ] : 0.f;
    float x2 = (t0 >= 1) ? src[(size_t)(t0 - 1) * DPROJ] : 0.f;
    for (int t = t0; t < t0 + CCHUNK; t++) {
        float x3 = src[(size_t)t * DPROJ];
        float v = bias + x0 * w0 + x1 * w1 + x2 * w2 + x3 * w3;
        v = v * sigmoidf_(v);
        dst[(size_t)t * DCONV] = v;
        x0 = x1; x1 = x2; x2 = x3;
    }
}

// ---------------------------------------------------------------------------
// Sequential selective scan. Block = (b, head), 64 threads (thread = p).
// ---------------------------------------------------------------------------
__global__ __launch_bounds__(64)
void scan_kernel(const float* __restrict__ Dvec) {
    int bh = blockIdx.x;
    int b = bh >> 6, hh = bh & 63;
    int p = threadIdx.x;

    __shared__ __align__(16) float sB[2][64];
    __shared__ __align__(16) float sC[2][64];
    __shared__ __align__(16) float sX[2][64];
    __shared__ float sS[2][2];

    float st[64];
#pragma unroll
    for (int n = 0; n < 64; n++) st[n] = 0.f;
    float Dh = Dvec[hh];

    const size_t base = (size_t)b * T_ * DCONV;
    {
        sX[0][p] = g_xbc[base + hh * 64 + p];
        sB[0][p] = g_xbc[base + 4096 + p];
        sC[0][p] = g_xbc[base + 4160 + p];
        if (p < 2) {
            int rr = b * T_;
            sS[0][p] = (p == 0) ? g_dA[rr * NH + hh] : g_dt[rr * NH + hh];
        }
    }

    for (int t = 0; t < T_; t++) {
        int buf = t & 1;
        __syncthreads();
        if (t + 1 < T_) {
            size_t rq = base + (size_t)(t + 1) * DCONV;
            sX[buf ^ 1][p] = g_xbc[rq + hh * 64 + p];
            sB[buf ^ 1][p] = g_xbc[rq + 4096 + p];
            sC[buf ^ 1][p] = g_xbc[rq + 4160 + p];
            if (p < 2) {
                int rr = b * T_ + t + 1;
                sS[buf ^ 1][p] = (p == 0) ? g_dA[rr * NH + hh] : g_dt[rr * NH + hh];
            }
        }
        float dAv = sS[buf][0];
        float dtx = sS[buf][1] * sX[buf][p];
        float acc = 0.f;
#pragma unroll
        for (int q = 0; q < 16; q++) {
            float4 b4 = *reinterpret_cast<const float4*>(&sB[buf][q * 4]);
            float4 c4 = *reinterpret_cast<const float4*>(&sC[buf][q * 4]);
            st[q * 4 + 0] = st[q * 4 + 0] * dAv + dtx * b4.x;
            st[q * 4 + 1] = st[q * 4 + 1] * dAv + dtx * b4.y;
            st[q * 4 + 2] = st[q * 4 + 2] * dAv + dtx * b4.z;
            st[q * 4 + 3] = st[q * 4 + 3] * dAv + dtx * b4.w;
            acc = fmaf(st[q * 4 + 0], c4.x, acc);
            acc = fmaf(st[q * 4 + 1], c4.y, acc);
            acc = fmaf(st[q * 4 + 2], c4.z, acc);
            acc = fmaf(st[q * 4 + 3], c4.w, acc);
        }
        g_y[(size_t)(b * T_ + t) * DIN + hh * 64 + p] = acc + Dh * sX[buf][p];
    }
}

// ---------------------------------------------------------------------------
// y = y * silu(z); RMSNorm * norm_w. Block per token.
// ---------------------------------------------------------------------------
__global__ void gate_rms_kernel(const float* __restrict__ norm_w) {
    int r = blockIdx.x;
    float ss = 0.f;
    for (int i = threadIdx.x; i < DIN; i += blockDim.x) {
        float zv = g_zx[(size_t)r * DPROJ + i];
        float g = g_y[(size_t)r * DIN + i] * zv * sigmoidf_(zv);
        g_y[(size_t)r * DIN + i] = g;
        ss += g * g;
    }
    __shared__ float sh[32];
    int lane = threadIdx.x & 31, wid = threadIdx.x >> 5;
#pragma unroll
    for (int o = 16; o; o >>= 1) ss += __shfl_xor_sync(0xffffffffu, ss, o);
    if (lane == 0) sh[wid] = ss;
    __syncthreads();
    __shared__ float sc;
    if (threadIdx.x == 0) {
        float tot = 0.f;
        int nw = blockDim.x >> 5;
        for (int i = 0; i < nw; i++) tot += sh[i];
        sc = rsqrtf(tot / DIN + 1e-5f);
    }
    __syncthreads();
    float s = sc;
    for (int i = threadIdx.x; i < DIN; i += blockDim.x)
        g_y[(size_t)r * DIN + i] *= s * norm_w[i];
}

// ---------------------------------------------------------------------------
// launch
// ---------------------------------------------------------------------------
extern "C" void kernel_launch(void* const* d_in, const int* in_sizes, int n_in,
                              void* d_out, int out_size) {
    const float* x          = (const float*)d_in[0];
    const float* ln_w       = (const float*)d_in[1];
    const float* ln_b       = (const float*)d_in[2];
    const float* in_proj_w  = (const float*)d_in[3];
    const float* conv_w     = (const float*)d_in[4];
    const float* conv_b     = (const float*)d_in[5];
    const float* dt_bias    = (const float*)d_in[6];
    const float* A_log      = (const float*)d_in[7];
    const float* Dv         = (const float*)d_in[8];
    const float* norm_w     = (const float*)d_in[9];
    const float* out_proj_w = (const float*)d_in[10];
    float* out = (float*)d_out;

    ln_kernel<<<NTOK, 256>>>(x, ln_w, ln_b);
    dtexact_kernel<<<NTOK / DTTOK, 256>>>(in_proj_w, dt_bias, A_log);
    gemm1_tc<<<dim3((DPROJ + 127) / 128, NTOK / 128), 256>>>(in_proj_w);
    conv_kernel<<<dim3((DCONV + 255) / 256, B_ * 8), 256>>>(conv_w, conv_b);
    scan_kernel<<<B_ * NH, 64>>>(Dv);
    gate_rms_kernel<<<NTOK, 256>>>(norm_w);
    gemm2_tc<<<dim3(DM / 128, NTOK / 128), 256>>>(out_proj_w, x, out);
}